// round 9
// baseline (speedup 1.0000x reference)
#include <cuda_runtime.h>
#include <cuda_bf16.h>

#define BB 8
#define SS 2048
#define EE 1024
#define HH 128

typedef unsigned int u32;

// ---------------- device scratch ----------------
__device__ __nv_bfloat16 g_xh[BB*SS*EE], g_xl[BB*SS*EE];     // X split [s][e]
__device__ __nv_bfloat16 g_wth[3][HH*EE], g_wtl[3][HH*EE];   // W^T split [h][e]
__device__ __nv_bfloat16 g_qh[BB*SS*HH], g_ql[BB*SS*HH];     // Q [s][h]
__device__ __nv_bfloat16 g_kh[BB*SS*HH];                     // K hi [s][h]
__device__ __nv_bfloat16 g_vth[BB*HH*SS], g_vtl[BB*HH*SS];   // V^T [b][h][s]
__device__ u32 g_mask[BB*SS*SS/32];                          // dropout keep bits

// ---------------- helpers ----------------
__device__ __forceinline__ u32 smem_u32(const void* p) {
    u32 a;
    asm("{ .reg .u64 t; cvta.to.shared.u64 t, %1; cvt.u32.u64 %0, t; }" : "=r"(a) : "l"(p));
    return a;
}
__device__ __forceinline__ void cpa16(u32 dst, const void* src) {
    asm volatile("cp.async.cg.shared.global [%0], [%1], 16;" :: "r"(dst), "l"(src));
}
#define CP_COMMIT() asm volatile("cp.async.commit_group;" ::: "memory")
#define CP_WAIT(n)  asm volatile("cp.async.wait_group %0;" :: "n"(n) : "memory")

__device__ __forceinline__ u32 packbf(float lo, float hi) {
    u32 r;
    asm("cvt.rn.bf16x2.f32 %0, %1, %2;" : "=r"(r) : "f"(hi), "f"(lo));
    return r;
}
__device__ __forceinline__ u32 packlo(float p0, float p1, u32 h) {
    float r0 = p0 - __uint_as_float(h << 16);
    float r1 = p1 - __uint_as_float(h & 0xffff0000u);
    return packbf(r0, r1);
}
__device__ __forceinline__ void mma16816(float* c, u32 a0, u32 a1, u32 a2, u32 a3,
                                         u32 b0, u32 b1) {
    asm volatile("mma.sync.aligned.m16n8k16.row.col.f32.bf16.bf16.f32 "
                 "{%0,%1,%2,%3},{%4,%5,%6,%7},{%8,%9},{%0,%1,%2,%3};"
                 : "+f"(c[0]), "+f"(c[1]), "+f"(c[2]), "+f"(c[3])
                 : "r"(a0), "r"(a1), "r"(a2), "r"(a3), "r"(b0), "r"(b1));
}
__device__ __forceinline__ void mmaA(float* c, const uint4& a, u32 b0, u32 b1) {
    mma16816(c, a.x, a.y, a.z, a.w, b0, b1);
}
__device__ __forceinline__ uint4 ldm4(u32 addr) {
    uint4 r;
    asm volatile("ldmatrix.sync.aligned.m8n8.x4.shared.b16 {%0,%1,%2,%3}, [%4];"
                 : "=r"(r.x), "=r"(r.y), "=r"(r.z), "=r"(r.w) : "r"(addr));
    return r;
}

// ---------------------------------------------------------------------------
// prep kernels
// ---------------------------------------------------------------------------
__global__ __launch_bounds__(256) void xprep_kernel(const float* __restrict__ x) {
    size_t i = ((size_t)blockIdx.x * 256 + threadIdx.x) * 4;
    float4 v = *(const float4*)(x + i);
    u32 h01 = packbf(v.x, v.y), h23 = packbf(v.z, v.w);
    u32 l01 = packlo(v.x, v.y, h01), l23 = packlo(v.z, v.w, h23);
    *(uint2*)&g_xh[i] = make_uint2(h01, h23);
    *(uint2*)&g_xl[i] = make_uint2(l01, l23);
}
__global__ __launch_bounds__(256) void wprep_kernel(
    const float* __restrict__ wq, const float* __restrict__ wk,
    const float* __restrict__ wv)
{
    int idx = blockIdx.x * 256 + threadIdx.x;   // e*128+h
    int e = idx >> 7, h = idx & 127;
    int o = h * EE + e;
    const float* src[3] = {wq, wk, wv};
#pragma unroll
    for (int m = 0; m < 3; m++) {
        float v = src[m][idx];
        __nv_bfloat16 hi = __float2bfloat16_rn(v);
        g_wth[m][o] = hi;
        g_wtl[m][o] = __float2bfloat16_rn(v - __bfloat162float(hi));
    }
}
__global__ __launch_bounds__(256) void maskprep_kernel(const float* __restrict__ du) {
    size_t gid = (size_t)blockIdx.x * 256 + threadIdx.x;
    u32 m = __ballot_sync(0xffffffffu, du[gid] >= 0.1f);
    if ((threadIdx.x & 31) == 0) g_mask[gid >> 5] = m;
}

// ---------------------------------------------------------------------------
// proj: C[128 x 128] = X @ W (q/k/v by blockIdx.y). q/k: 2-pass (Xh*Wh + Xh*Wl);
// v: 3-pass (+ Xl*Wh). 512 threads: 16 warps = 8 M-warps x 2 N-warps.
// Warp tile 16x64. B frags reg-cached across passes. cp.async 2-stage.
// smem tile: [128][72] bf16 (144B pitch).
// ---------------------------------------------------------------------------
#define PJ_T 18432            // 128*72*2
#define PJ_STG (4 * PJ_T)     // Xh,Xl,Wh,Wl slots
#define PROJ_SMEM (2 * PJ_STG)

__device__ __forceinline__ void chunk_load512(u32 dst, const __nv_bfloat16* src) {
    int tid = threadIdx.x;
#pragma unroll
    for (int i = 0; i < 2; i++) {
        int id = tid + i * 512;
        int r = id >> 3, q = id & 7;
        cpa16(dst + r * 144 + q * 16, (const char*)src + (size_t)r * 2048 + q * 16);
    }
}

__global__ __launch_bounds__(512) void proj_kernel(void) {
    extern __shared__ char sm[];
    const u32 sb = smem_u32(sm);
    const int tid = threadIdx.x, w = tid >> 5, lane = tid & 31;
    const int wy = w >> 1, wx = w & 1;
    const int g = lane >> 2, tg = lane & 3;
    const int which = blockIdx.y;
    const int row0 = blockIdx.x * 128;
    const bool isv = (which == 2);

    const __nv_bfloat16* xh = g_xh + (size_t)row0 * EE;
    const __nv_bfloat16* xl = g_xl + (size_t)row0 * EE;
    const __nv_bfloat16* wth = g_wth[which];
    const __nv_bfloat16* wtl = g_wtl[which];

    const u32 aoff = (u32)((wy*16 + (lane & 15)) * 144 + ((lane >> 4) & 1) * 16);
    const u32 boff = (u32)((wx*64 + (lane & 7) + ((lane >> 4) & 1) * 8) * 144 + ((lane >> 3) & 1) * 16);

    float c[8][4];
#pragma unroll
    for (int n = 0; n < 8; n++)
#pragma unroll
        for (int j = 0; j < 4; j++) c[n][j] = 0.0f;

    chunk_load512(sb, xh);
    if (isv) chunk_load512(sb + PJ_T, xl);
    chunk_load512(sb + 2*PJ_T, wth);
    chunk_load512(sb + 3*PJ_T, wtl);
    CP_COMMIT();

    for (int ch = 0; ch < 16; ch++) {
        int cur = ch & 1;
        if (ch < 15) {
            u32 nb = sb + (cur ^ 1) * PJ_STG;
            chunk_load512(nb, xh + (ch+1)*64);
            if (isv) chunk_load512(nb + PJ_T, xl + (ch+1)*64);
            chunk_load512(nb + 2*PJ_T, wth + (ch+1)*64);
            chunk_load512(nb + 3*PJ_T, wtl + (ch+1)*64);
            CP_COMMIT();
            CP_WAIT(1);
        } else {
            CP_WAIT(0);
        }
        __syncthreads();
        const u32 Xh = sb + cur * PJ_STG;
        const u32 Xl = Xh + PJ_T;
        const u32 Wh = Xh + 2*PJ_T;
        const u32 Wl = Xh + 3*PJ_T;
#pragma unroll
        for (int kt = 0; kt < 4; kt++) {
            uint4 AH = ldm4(Xh + aoff + kt*32);
            uint4 bh[4], bl[4];
#pragma unroll
            for (int np = 0; np < 4; np++) bh[np] = ldm4(Wh + boff + np*2304 + kt*32);
#pragma unroll
            for (int np = 0; np < 4; np++) bl[np] = ldm4(Wl + boff + np*2304 + kt*32);
            // pass 1: Xh * Wh
#pragma unroll
            for (int np = 0; np < 4; np++) {
                mmaA(c[2*np], AH, bh[np].x, bh[np].y);
                mmaA(c[2*np+1], AH, bh[np].z, bh[np].w);
            }
            // pass 2: Xh * Wl
#pragma unroll
            for (int np = 0; np < 4; np++) {
                mmaA(c[2*np], AH, bl[np].x, bl[np].y);
                mmaA(c[2*np+1], AH, bl[np].z, bl[np].w);
            }
            if (isv) {   // pass 3: Xl * Wh
                uint4 AL = ldm4(Xl + aoff + kt*32);
#pragma unroll
                for (int np = 0; np < 4; np++) {
                    mmaA(c[2*np], AL, bh[np].x, bh[np].y);
                    mmaA(c[2*np+1], AL, bh[np].z, bh[np].w);
                }
            }
        }
        __syncthreads();
    }

    if (which < 2) {
        __nv_bfloat16* dh = which ? g_kh : g_qh;
        size_t rA = (size_t)(row0 + wy*16 + g) * HH;
        size_t rB = rA + 8 * HH;
#pragma unroll
        for (int n = 0; n < 8; n++) {
            int col = wx*64 + n*8 + tg*2;
            u32 h0 = packbf(c[n][0], c[n][1]);
            u32 h1 = packbf(c[n][2], c[n][3]);
            *(u32*)&dh[rA + col] = h0;
            *(u32*)&dh[rB + col] = h1;
            if (which == 0) {
                *(u32*)&g_ql[rA + col] = packlo(c[n][0], c[n][1], h0);
                *(u32*)&g_ql[rB + col] = packlo(c[n][2], c[n][3], h1);
            }
        }
    } else {
        float* Cs = (float*)sm;   // [128][132]
#pragma unroll
        for (int n = 0; n < 8; n++) {
            int col = wx*64 + n*8 + tg*2;
            Cs[(wy*16 + g) * 132 + col]     = c[n][0];
            Cs[(wy*16 + g) * 132 + col + 1] = c[n][1];
            Cs[(wy*16 + g + 8) * 132 + col]     = c[n][2];
            Cs[(wy*16 + g + 8) * 132 + col + 1] = c[n][3];
        }
        __syncthreads();
        int h = tid >> 2, q4 = tid & 3;
        int b = row0 >> 11, s0 = row0 & 2047;
        union { __nv_bfloat16 v[32]; uint4 u[4]; } Hh, Ll;
#pragma unroll
        for (int j = 0; j < 32; j++) {
            float f = Cs[(q4*32 + j) * 132 + h];
            __nv_bfloat16 hi = __float2bfloat16_rn(f);
            Hh.v[j] = hi;
            Ll.v[j] = __float2bfloat16_rn(f - __bfloat162float(hi));
        }
        size_t ob = ((size_t)(b*HH + h)) * SS + s0 + q4*32;
#pragma unroll
        for (int j = 0; j < 4; j++) {
            *(uint4*)&g_vth[ob + j*8] = Hh.u[j];
            *(uint4*)&g_vtl[ob + j*8] = Ll.u[j];
        }
    }
}

// ---------------------------------------------------------------------------
// attn: CTA = 128 Q rows x one batch. 8 warps, warp = 16 rows.
// QK 2-pass with K frags reg-cached; PV 3-pass with Vh frags reg-cached.
// Dropout via prepacked bitmask. smem: Qh,Ql,Kh,Vth,Vtl [128][136] (272B pitch).
// ---------------------------------------------------------------------------
#define AT_T 34816            // 128*136*2
#define ATT_SMEM (5 * AT_T)

__device__ __forceinline__ void tile_load(u32 dst, const __nv_bfloat16* src,
                                          int stride_elems) {
    int tid = threadIdx.x;
#pragma unroll
    for (int i = 0; i < 8; i++) {
        int id = tid + i * 256;
        int r = id >> 4, q = id & 15;
        cpa16(dst + r * 272 + q * 16,
              (const char*)src + (size_t)r * stride_elems * 2 + q * 16);
    }
}

__global__ __launch_bounds__(256) void attn_kernel(float* __restrict__ out)
{
    extern __shared__ char sm[];
    const u32 sb = smem_u32(sm);
    const int tid = threadIdx.x, w = tid >> 5, lane = tid & 31;
    const int g = lane >> 2, tg = lane & 3;
    const int b = blockIdx.y;
    const int q0 = blockIdx.x * 128;

    const u32 Qh = sb, Ql = sb + AT_T, Kh = sb + 2*AT_T;
    const u32 Vh = sb + 3*AT_T, Vl = sb + 4*AT_T;

    const u32 aoff = (u32)((w*16 + (lane & 15)) * 272 + ((lane >> 4) & 1) * 16);
    const u32 boff = (u32)(((lane & 7) + ((lane >> 4) & 1) * 8) * 272 + ((lane >> 3) & 1) * 16);

    const size_t qoff = (size_t)(b*SS + q0) * HH;
    tile_load(Qh, g_qh + qoff, HH);
    tile_load(Ql, g_ql + qoff, HH);
    tile_load(Kh, g_kh + (size_t)(b*SS) * HH, HH);
    CP_COMMIT();

    float o[16][4];
#pragma unroll
    for (int n = 0; n < 16; n++)
#pragma unroll
        for (int j = 0; j < 4; j++) o[n][j] = 0.0f;
    float lsumA = 0.0f, lsumB = 0.0f;

    const float SC = 0.03125f;        // 1024^-0.5
    const float INVK = 1.0f / 0.9f;
    const u32* mrowA = g_mask + ((size_t)(b*SS) + q0 + w*16 + g) * (SS/32);
    const u32* mrowB = mrowA + 8 * (SS/32);

    CP_WAIT(0);
    __syncthreads();

    for (int t = 0; t < 16; t++) {
        const int k0 = t * 128;
        // V(t) load overlaps QK(t)
        tile_load(Vh, g_vth + (size_t)(b*HH) * SS + k0, SS);
        tile_load(Vl, g_vtl + (size_t)(b*HH) * SS + k0, SS);
        CP_COMMIT();
        uint4 mA = *(const uint4*)(mrowA + t*4);
        uint4 mB = *(const uint4*)(mrowB + t*4);

        float c[16][4];
#pragma unroll
        for (int n = 0; n < 16; n++)
#pragma unroll
            for (int j = 0; j < 4; j++) c[n][j] = 0.0f;

#pragma unroll
        for (int kt = 0; kt < 8; kt++) {
            uint4 AH = ldm4(Qh + aoff + kt*32);
            uint4 AL = ldm4(Ql + aoff + kt*32);
            uint4 kb[8];
#pragma unroll
            for (int np = 0; np < 8; np++) kb[np] = ldm4(Kh + boff + np*4352 + kt*32);
            // pass 1: Qh * Kh
#pragma unroll
            for (int np = 0; np < 8; np++) {
                mmaA(c[2*np], AH, kb[np].x, kb[np].y);
                mmaA(c[2*np+1], AH, kb[np].z, kb[np].w);
            }
            // pass 2: Ql * Kh (reg-cached frags)
#pragma unroll
            for (int np = 0; np < 8; np++) {
                mmaA(c[2*np], AL, kb[np].x, kb[np].y);
                mmaA(c[2*np+1], AL, kb[np].z, kb[np].w);
            }
        }

        CP_WAIT(0);          // V(t) ready
        __syncthreads();     // all warps done reading K(t)
        if (t < 15) {
            tile_load(Kh, g_kh + (size_t)(b*SS + k0 + 128) * HH, HH);
            CP_COMMIT();
        }

        // softmax + dropout(numerator only) + PV
#pragma unroll
        for (int kt = 0; kt < 8; kt++) {
            u32 ph[4], pl[4];
            u32 wa = ((const u32*)&mA)[kt >> 1];
            u32 wb = ((const u32*)&mB)[kt >> 1];
#pragma unroll
            for (int half = 0; half < 2; half++) {
                int n = 2*kt + half;
                int sh = (kt & 1)*16 + half*8 + tg*2;
                float p0 = __expf(c[n][0] * SC), p1 = __expf(c[n][1] * SC);
                float p2 = __expf(c[n][2] * SC), p3 = __expf(c[n][3] * SC);
                lsumA += p0 + p1;
                lsumB += p2 + p3;
                p0 *= ((wa >> sh) & 1)     ? INVK : 0.0f;
                p1 *= ((wa >> (sh+1)) & 1) ? INVK : 0.0f;
                p2 *= ((wb >> sh) & 1)     ? INVK : 0.0f;
                p3 *= ((wb >> (sh+1)) & 1) ? INVK : 0.0f;
                ph[2*half]     = packbf(p0, p1);
                pl[2*half]     = packlo(p0, p1, ph[2*half]);
                ph[2*half + 1] = packbf(p2, p3);
                pl[2*half + 1] = packlo(p2, p3, ph[2*half + 1]);
            }
            uint4 vb[8];
#pragma unroll
            for (int np = 0; np < 8; np++) vb[np] = ldm4(Vh + boff + np*4352 + kt*32);
            // pass 1: Ph * Vh
#pragma unroll
            for (int np = 0; np < 8; np++) {
                mma16816(o[2*np], ph[0], ph[1], ph[2], ph[3], vb[np].x, vb[np].y);
                mma16816(o[2*np+1], ph[0], ph[1], ph[2], ph[3], vb[np].z, vb[np].w);
            }
            // pass 2: Ph * Vl (inline loads)
#pragma unroll
            for (int np = 0; np < 8; np++) {
                uint4 B = ldm4(Vl + boff + np*4352 + kt*32);
                mma16816(o[2*np], ph[0], ph[1], ph[2], ph[3], B.x, B.y);
                mma16816(o[2*np+1], ph[0], ph[1], ph[2], ph[3], B.z, B.w);
            }
            // pass 3: Pl * Vh (reg-cached frags)
#pragma unroll
            for (int np = 0; np < 8; np++) {
                mma16816(o[2*np], pl[0], pl[1], pl[2], pl[3], vb[np].x, vb[np].y);
                mma16816(o[2*np+1], pl[0], pl[1], pl[2], pl[3], vb[np].z, vb[np].w);
            }
        }
        if (t < 15) CP_WAIT(0);   // K(t+1) ready
        __syncthreads();          // V buffer reuse safety
    }

    // per-row softmax denominators: reduce over quad lanes
#pragma unroll
    for (int off = 1; off <= 2; off <<= 1) {
        lsumA += __shfl_xor_sync(0xffffffffu, lsumA, off);
        lsumB += __shfl_xor_sync(0xffffffffu, lsumB, off);
    }
    const float invA = 1.0f / lsumA, invB = 1.0f / lsumB;

    float* oA = out + ((size_t)(b*SS) + q0 + w*16 + g) * HH;
    float* oB = oA + 8 * HH;
#pragma unroll
    for (int n = 0; n < 16; n++) {
        int col = n*8 + tg*2;
        *(float2*)(oA + col) = make_float2(o[n][0] * invA, o[n][1] * invA);
        *(float2*)(oB + col) = make_float2(o[n][2] * invB, o[n][3] * invB);
    }
}

extern "C" void kernel_launch(void* const* d_in, const int* in_sizes, int n_in,
                              void* d_out, int out_size)
{
    const float* x  = (const float*)d_in[0];
    const float* wq = (const float*)d_in[1];
    const float* wk = (const float*)d_in[2];
    const float* wv = (const float*)d_in[3];
    const float* du = (const float*)d_in[4];
    float* out = (float*)d_out;

    cudaFuncSetAttribute(proj_kernel, cudaFuncAttributeMaxDynamicSharedMemorySize, PROJ_SMEM);
    cudaFuncSetAttribute(attn_kernel, cudaFuncAttributeMaxDynamicSharedMemorySize, ATT_SMEM);

    xprep_kernel<<<(BB*SS*EE/4 + 255) / 256, 256>>>(x);
    wprep_kernel<<<EE*HH / 256, 256>>>(wq, wk, wv);
    maskprep_kernel<<<(int)((size_t)BB*SS*SS / 256), 256>>>(du);
    dim3 g1(BB*SS / 128, 3);
    proj_kernel<<<g1, 512, PROJ_SMEM>>>();
    dim3 g2(SS / 128, BB);
    attn_kernel<<<g2, 256, ATT_SMEM>>>(out);
}

// round 10
// speedup vs baseline: 1.0431x; 1.0431x over previous
#include <cuda_runtime.h>
#include <cuda_bf16.h>

#define BB 8
#define SS 2048
#define EE 1024
#define HH 128

typedef unsigned int u32;

// ---------------- device scratch ----------------
__device__ __nv_bfloat16 g_xh[BB*SS*EE], g_xl[BB*SS*EE];     // X split [s][e]
__device__ __nv_bfloat16 g_wth[3][HH*EE], g_wtl[3][HH*EE];   // W^T split [h][e]
__device__ __nv_bfloat16 g_qh[BB*SS*HH], g_ql[BB*SS*HH];     // Q [s][h]
__device__ __nv_bfloat16 g_kh[BB*SS*HH];                     // K hi [s][h]
__device__ __nv_bfloat16 g_vth[BB*HH*SS], g_vtl[BB*HH*SS];   // V^T [b][h][s]
__device__ u32 g_mask[BB*SS*SS/32];                          // dropout keep bits

// ---------------- helpers ----------------
__device__ __forceinline__ u32 smem_u32(const void* p) {
    u32 a;
    asm("{ .reg .u64 t; cvta.to.shared.u64 t, %1; cvt.u32.u64 %0, t; }" : "=r"(a) : "l"(p));
    return a;
}
__device__ __forceinline__ void cpa16(u32 dst, const void* src) {
    asm volatile("cp.async.cg.shared.global [%0], [%1], 16;" :: "r"(dst), "l"(src));
}
#define CP_COMMIT() asm volatile("cp.async.commit_group;" ::: "memory")
#define CP_WAIT(n)  asm volatile("cp.async.wait_group %0;" :: "n"(n) : "memory")

__device__ __forceinline__ u32 packbf(float lo, float hi) {
    u32 r;
    asm("cvt.rn.bf16x2.f32 %0, %1, %2;" : "=r"(r) : "f"(hi), "f"(lo));
    return r;
}
__device__ __forceinline__ u32 packlo(float p0, float p1, u32 h) {
    float r0 = p0 - __uint_as_float(h << 16);
    float r1 = p1 - __uint_as_float(h & 0xffff0000u);
    return packbf(r0, r1);
}
__device__ __forceinline__ void mma16816(float* c, u32 a0, u32 a1, u32 a2, u32 a3,
                                         u32 b0, u32 b1) {
    asm volatile("mma.sync.aligned.m16n8k16.row.col.f32.bf16.bf16.f32 "
                 "{%0,%1,%2,%3},{%4,%5,%6,%7},{%8,%9},{%0,%1,%2,%3};"
                 : "+f"(c[0]), "+f"(c[1]), "+f"(c[2]), "+f"(c[3])
                 : "r"(a0), "r"(a1), "r"(a2), "r"(a3), "r"(b0), "r"(b1));
}
__device__ __forceinline__ void mmaA(float* c, const uint4& a, u32 b0, u32 b1) {
    mma16816(c, a.x, a.y, a.z, a.w, b0, b1);
}
__device__ __forceinline__ uint4 ldm4(u32 addr) {
    uint4 r;
    asm volatile("ldmatrix.sync.aligned.m8n8.x4.shared.b16 {%0,%1,%2,%3}, [%4];"
                 : "=r"(r.x), "=r"(r.y), "=r"(r.z), "=r"(r.w) : "r"(addr));
    return r;
}

// ---------------------------------------------------------------------------
// prep kernels
// ---------------------------------------------------------------------------
__global__ __launch_bounds__(256) void xprep_kernel(const float* __restrict__ x) {
    size_t i = ((size_t)blockIdx.x * 256 + threadIdx.x) * 4;
    float4 v = *(const float4*)(x + i);
    u32 h01 = packbf(v.x, v.y), h23 = packbf(v.z, v.w);
    u32 l01 = packlo(v.x, v.y, h01), l23 = packlo(v.z, v.w, h23);
    *(uint2*)&g_xh[i] = make_uint2(h01, h23);
    *(uint2*)&g_xl[i] = make_uint2(l01, l23);
}
__global__ __launch_bounds__(256) void wprep_kernel(
    const float* __restrict__ wq, const float* __restrict__ wk,
    const float* __restrict__ wv)
{
    int idx = blockIdx.x * 256 + threadIdx.x;   // e*128+h
    int e = idx >> 7, h = idx & 127;
    int o = h * EE + e;
    const float* src[3] = {wq, wk, wv};
#pragma unroll
    for (int m = 0; m < 3; m++) {
        float v = src[m][idx];
        __nv_bfloat16 hi = __float2bfloat16_rn(v);
        g_wth[m][o] = hi;
        g_wtl[m][o] = __float2bfloat16_rn(v - __bfloat162float(hi));
    }
}
__global__ __launch_bounds__(256) void maskprep_kernel(const float* __restrict__ du) {
    size_t gid = (size_t)blockIdx.x * 256 + threadIdx.x;
    u32 m = __ballot_sync(0xffffffffu, du[gid] >= 0.1f);
    if ((threadIdx.x & 31) == 0) g_mask[gid >> 5] = m;
}

// ---------------------------------------------------------------------------
// proj: 256 threads, 8 warps, warp tile M=64 x N=32 (wy = w>>2 in {0,1}: 64-row
// half; wx = w&3: 32-col quarter).  blockIdx.y==0: merged q+k CTA (2-pass each,
// shares X A-frags).  blockIdx.y==1: v CTA (3-pass) with transposed V^T store.
// smem: K-chunk 64, tiles [128][72] bf16 (144B pitch), 2-stage cp.async.
// qk stage = {Xh, Wqh, Wql, Wkh, Wkl}; v stage = {Xh, Xl, Wvh, Wvl}.
// ---------------------------------------------------------------------------
#define PJ_T 18432            // 128*72*2
#define PROJ_SMEM (2 * 5 * PJ_T)   // 184320 (qk uses 5 tiles/stage, v uses 4)

__device__ __forceinline__ void chunk_load(u32 dst, const __nv_bfloat16* src) {
    int tid = threadIdx.x;
#pragma unroll
    for (int i = 0; i < 4; i++) {
        int id = tid + i * 256;
        int r = id >> 3, q = id & 7;
        cpa16(dst + r * 144 + q * 16, (const char*)src + (size_t)r * 2048 + q * 16);
    }
}

__global__ __launch_bounds__(256) void proj_kernel(void) {
    extern __shared__ char sm[];
    const u32 sb = smem_u32(sm);
    const int tid = threadIdx.x, w = tid >> 5, lane = tid & 31;
    const int wy = w >> 2, wx = w & 3;
    const int g = lane >> 2, tg = lane & 3;
    const int row0 = blockIdx.x * 128;
    const bool isqk = (blockIdx.y == 0);

    const __nv_bfloat16* xh = g_xh + (size_t)row0 * EE;
    const __nv_bfloat16* xl = g_xl + (size_t)row0 * EE;

    const u32 aoff = (u32)((wy*64 + (lane & 15)) * 144 + ((lane >> 4) & 1) * 16);
    const u32 boff = (u32)((wx*32 + (lane & 7) + ((lane >> 4) & 1) * 8) * 144
                           + ((lane >> 3) & 1) * 16);

    float c0[16][4], c1[16][4];
#pragma unroll
    for (int n = 0; n < 16; n++)
#pragma unroll
        for (int j = 0; j < 4; j++) { c0[n][j] = 0.0f; c1[n][j] = 0.0f; }

    const u32 STG = (isqk ? 5u : 4u) * PJ_T;

    if (isqk) {
        chunk_load(sb,          xh);
        chunk_load(sb + PJ_T,   g_wth[0]);
        chunk_load(sb + 2*PJ_T, g_wtl[0]);
        chunk_load(sb + 3*PJ_T, g_wth[1]);
        chunk_load(sb + 4*PJ_T, g_wtl[1]);
    } else {
        chunk_load(sb,          xh);
        chunk_load(sb + PJ_T,   xl);
        chunk_load(sb + 2*PJ_T, g_wth[2]);
        chunk_load(sb + 3*PJ_T, g_wtl[2]);
    }
    CP_COMMIT();

    for (int ch = 0; ch < 16; ch++) {
        int cur = ch & 1;
        if (ch < 15) {
            u32 nb = sb + (cur ^ 1) * STG;
            int o = (ch + 1) * 64;
            if (isqk) {
                chunk_load(nb,          xh + o);
                chunk_load(nb + PJ_T,   g_wth[0] + o);
                chunk_load(nb + 2*PJ_T, g_wtl[0] + o);
                chunk_load(nb + 3*PJ_T, g_wth[1] + o);
                chunk_load(nb + 4*PJ_T, g_wtl[1] + o);
            } else {
                chunk_load(nb,          xh + o);
                chunk_load(nb + PJ_T,   xl + o);
                chunk_load(nb + 2*PJ_T, g_wth[2] + o);
                chunk_load(nb + 3*PJ_T, g_wtl[2] + o);
            }
            CP_COMMIT();
            CP_WAIT(1);
        } else {
            CP_WAIT(0);
        }
        __syncthreads();
        const u32 base = sb + cur * STG;

        if (isqk) {
#pragma unroll
            for (int kt = 0; kt < 4; kt++) {
                uint4 A[4];
#pragma unroll
                for (int mf = 0; mf < 4; mf++)
                    A[mf] = ldm4(base + aoff + mf*2304 + kt*32);
                // pass: q hi
                {
                    uint4 B0 = ldm4(base + PJ_T + boff + kt*32);
                    uint4 B1 = ldm4(base + PJ_T + boff + 2304 + kt*32);
#pragma unroll
                    for (int mf = 0; mf < 4; mf++) {
                        mmaA(c0[mf*4+0], A[mf], B0.x, B0.y);
                        mmaA(c0[mf*4+1], A[mf], B0.z, B0.w);
                        mmaA(c0[mf*4+2], A[mf], B1.x, B1.y);
                        mmaA(c0[mf*4+3], A[mf], B1.z, B1.w);
                    }
                }
                // pass: k hi (interleaved so q accums get 16-MMA spacing)
                {
                    uint4 B0 = ldm4(base + 3*PJ_T + boff + kt*32);
                    uint4 B1 = ldm4(base + 3*PJ_T + boff + 2304 + kt*32);
#pragma unroll
                    for (int mf = 0; mf < 4; mf++) {
                        mmaA(c1[mf*4+0], A[mf], B0.x, B0.y);
                        mmaA(c1[mf*4+1], A[mf], B0.z, B0.w);
                        mmaA(c1[mf*4+2], A[mf], B1.x, B1.y);
                        mmaA(c1[mf*4+3], A[mf], B1.z, B1.w);
                    }
                }
                // pass: q lo
                {
                    uint4 B0 = ldm4(base + 2*PJ_T + boff + kt*32);
                    uint4 B1 = ldm4(base + 2*PJ_T + boff + 2304 + kt*32);
#pragma unroll
                    for (int mf = 0; mf < 4; mf++) {
                        mmaA(c0[mf*4+0], A[mf], B0.x, B0.y);
                        mmaA(c0[mf*4+1], A[mf], B0.z, B0.w);
                        mmaA(c0[mf*4+2], A[mf], B1.x, B1.y);
                        mmaA(c0[mf*4+3], A[mf], B1.z, B1.w);
                    }
                }
                // pass: k lo
                {
                    uint4 B0 = ldm4(base + 4*PJ_T + boff + kt*32);
                    uint4 B1 = ldm4(base + 4*PJ_T + boff + 2304 + kt*32);
#pragma unroll
                    for (int mf = 0; mf < 4; mf++) {
                        mmaA(c1[mf*4+0], A[mf], B0.x, B0.y);
                        mmaA(c1[mf*4+1], A[mf], B0.z, B0.w);
                        mmaA(c1[mf*4+2], A[mf], B1.x, B1.y);
                        mmaA(c1[mf*4+3], A[mf], B1.z, B1.w);
                    }
                }
            }
        } else {
#pragma unroll
            for (int kt = 0; kt < 4; kt++) {
                uint4 A[4], AL[4];
#pragma unroll
                for (int mf = 0; mf < 4; mf++) {
                    A[mf]  = ldm4(base + aoff + mf*2304 + kt*32);
                    AL[mf] = ldm4(base + PJ_T + aoff + mf*2304 + kt*32);
                }
                uint4 Bh0 = ldm4(base + 2*PJ_T + boff + kt*32);
                uint4 Bh1 = ldm4(base + 2*PJ_T + boff + 2304 + kt*32);
                uint4 Bl0 = ldm4(base + 3*PJ_T + boff + kt*32);
                uint4 Bl1 = ldm4(base + 3*PJ_T + boff + 2304 + kt*32);
                // pass 1: Xh * Wh
#pragma unroll
                for (int mf = 0; mf < 4; mf++) {
                    mmaA(c0[mf*4+0], A[mf], Bh0.x, Bh0.y);
                    mmaA(c0[mf*4+1], A[mf], Bh0.z, Bh0.w);
                    mmaA(c0[mf*4+2], A[mf], Bh1.x, Bh1.y);
                    mmaA(c0[mf*4+3], A[mf], Bh1.z, Bh1.w);
                }
                // pass 2: Xh * Wl
#pragma unroll
                for (int mf = 0; mf < 4; mf++) {
                    mmaA(c0[mf*4+0], A[mf], Bl0.x, Bl0.y);
                    mmaA(c0[mf*4+1], A[mf], Bl0.z, Bl0.w);
                    mmaA(c0[mf*4+2], A[mf], Bl1.x, Bl1.y);
                    mmaA(c0[mf*4+3], A[mf], Bl1.z, Bl1.w);
                }
                // pass 3: Xl * Wh
#pragma unroll
                for (int mf = 0; mf < 4; mf++) {
                    mmaA(c0[mf*4+0], AL[mf], Bh0.x, Bh0.y);
                    mmaA(c0[mf*4+1], AL[mf], Bh0.z, Bh0.w);
                    mmaA(c0[mf*4+2], AL[mf], Bh1.x, Bh1.y);
                    mmaA(c0[mf*4+3], AL[mf], Bh1.z, Bh1.w);
                }
            }
        }
        __syncthreads();
    }

    if (isqk) {
#pragma unroll
        for (int mf = 0; mf < 4; mf++) {
            size_t rA = (size_t)(row0 + wy*64 + mf*16 + g) * HH;
            size_t rB = rA + 8 * HH;
#pragma unroll
            for (int f = 0; f < 4; f++) {
                int col = wx*32 + (f >> 1)*16 + (f & 1)*8 + tg*2;
                const float* cq = c0[mf*4 + f];
                const float* ck = c1[mf*4 + f];
                u32 qh0 = packbf(cq[0], cq[1]);
                u32 qh1 = packbf(cq[2], cq[3]);
                *(u32*)&g_qh[rA + col] = qh0;
                *(u32*)&g_qh[rB + col] = qh1;
                *(u32*)&g_ql[rA + col] = packlo(cq[0], cq[1], qh0);
                *(u32*)&g_ql[rB + col] = packlo(cq[2], cq[3], qh1);
                *(u32*)&g_kh[rA + col] = packbf(ck[0], ck[1]);
                *(u32*)&g_kh[rB + col] = packbf(ck[2], ck[3]);
            }
        }
    } else {
        float* Cs = (float*)sm;   // [128][132] f32 staging for transpose
#pragma unroll
        for (int mf = 0; mf < 4; mf++) {
            int r = wy*64 + mf*16 + g;
#pragma unroll
            for (int f = 0; f < 4; f++) {
                int col = wx*32 + (f >> 1)*16 + (f & 1)*8 + tg*2;
                const float* cv = c0[mf*4 + f];
                Cs[r * 132 + col]         = cv[0];
                Cs[r * 132 + col + 1]     = cv[1];
                Cs[(r + 8) * 132 + col]   = cv[2];
                Cs[(r + 8) * 132 + col + 1] = cv[3];
            }
        }
        __syncthreads();
        int h = tid >> 1, half = tid & 1;
        int b = row0 >> 11, s0 = row0 & 2047;
        union { __nv_bfloat16 v[64]; uint4 u[8]; } Hh, Ll;
#pragma unroll
        for (int j = 0; j < 64; j++) {
            float f = Cs[(half*64 + j) * 132 + h];
            __nv_bfloat16 hi = __float2bfloat16_rn(f);
            Hh.v[j] = hi;
            Ll.v[j] = __float2bfloat16_rn(f - __bfloat162float(hi));
        }
        size_t ob = ((size_t)(b*HH + h)) * SS + s0 + half*64;
#pragma unroll
        for (int j = 0; j < 8; j++) {
            *(uint4*)&g_vth[ob + j*8] = Hh.u[j];
            *(uint4*)&g_vtl[ob + j*8] = Ll.u[j];
        }
    }
}

// ---------------------------------------------------------------------------
// attn: CTA = 128 Q rows x one batch. 8 warps, warp = 16 rows.
// QK 2-pass with K frags reg-cached; PV 3-pass with Vh frags reg-cached.
// Dropout via prepacked bitmask. smem: Qh,Ql,Kh,Vth,Vtl [128][136] (272B pitch).
// ---------------------------------------------------------------------------
#define AT_T 34816            // 128*136*2
#define ATT_SMEM (5 * AT_T)

__device__ __forceinline__ void tile_load(u32 dst, const __nv_bfloat16* src,
                                          int stride_elems) {
    int tid = threadIdx.x;
#pragma unroll
    for (int i = 0; i < 8; i++) {
        int id = tid + i * 256;
        int r = id >> 4, q = id & 15;
        cpa16(dst + r * 272 + q * 16,
              (const char*)src + (size_t)r * stride_elems * 2 + q * 16);
    }
}

__global__ __launch_bounds__(256) void attn_kernel(float* __restrict__ out)
{
    extern __shared__ char sm[];
    const u32 sb = smem_u32(sm);
    const int tid = threadIdx.x, w = tid >> 5, lane = tid & 31;
    const int g = lane >> 2, tg = lane & 3;
    const int b = blockIdx.y;
    const int q0 = blockIdx.x * 128;

    const u32 Qh = sb, Ql = sb + AT_T, Kh = sb + 2*AT_T;
    const u32 Vh = sb + 3*AT_T, Vl = sb + 4*AT_T;

    const u32 aoff = (u32)((w*16 + (lane & 15)) * 272 + ((lane >> 4) & 1) * 16);
    const u32 boff = (u32)(((lane & 7) + ((lane >> 4) & 1) * 8) * 272 + ((lane >> 3) & 1) * 16);

    const size_t qoff = (size_t)(b*SS + q0) * HH;
    tile_load(Qh, g_qh + qoff, HH);
    tile_load(Ql, g_ql + qoff, HH);
    tile_load(Kh, g_kh + (size_t)(b*SS) * HH, HH);
    CP_COMMIT();

    float o[16][4];
#pragma unroll
    for (int n = 0; n < 16; n++)
#pragma unroll
        for (int j = 0; j < 4; j++) o[n][j] = 0.0f;
    float lsumA = 0.0f, lsumB = 0.0f;

    const float SC = 0.03125f;        // 1024^-0.5
    const float INVK = 1.0f / 0.9f;
    const u32* mrowA = g_mask + ((size_t)(b*SS) + q0 + w*16 + g) * (SS/32);
    const u32* mrowB = mrowA + 8 * (SS/32);

    CP_WAIT(0);
    __syncthreads();

    for (int t = 0; t < 16; t++) {
        const int k0 = t * 128;
        // V(t) load overlaps QK(t)
        tile_load(Vh, g_vth + (size_t)(b*HH) * SS + k0, SS);
        tile_load(Vl, g_vtl + (size_t)(b*HH) * SS + k0, SS);
        CP_COMMIT();
        uint4 mA = *(const uint4*)(mrowA + t*4);
        uint4 mB = *(const uint4*)(mrowB + t*4);

        float c[16][4];
#pragma unroll
        for (int n = 0; n < 16; n++)
#pragma unroll
            for (int j = 0; j < 4; j++) c[n][j] = 0.0f;

#pragma unroll
        for (int kt = 0; kt < 8; kt++) {
            uint4 AH = ldm4(Qh + aoff + kt*32);
            uint4 AL = ldm4(Ql + aoff + kt*32);
            uint4 kb[8];
#pragma unroll
            for (int np = 0; np < 8; np++) kb[np] = ldm4(Kh + boff + np*4352 + kt*32);
            // pass 1: Qh * Kh
#pragma unroll
            for (int np = 0; np < 8; np++) {
                mmaA(c[2*np], AH, kb[np].x, kb[np].y);
                mmaA(c[2*np+1], AH, kb[np].z, kb[np].w);
            }
            // pass 2: Ql * Kh (reg-cached frags)
#pragma unroll
            for (int np = 0; np < 8; np++) {
                mmaA(c[2*np], AL, kb[np].x, kb[np].y);
                mmaA(c[2*np+1], AL, kb[np].z, kb[np].w);
            }
        }

        CP_WAIT(0);          // V(t) ready
        __syncthreads();     // all warps done reading K(t)
        if (t < 15) {
            tile_load(Kh, g_kh + (size_t)(b*SS + k0 + 128) * HH, HH);
            CP_COMMIT();
        }

        // softmax + dropout(numerator only) + PV
#pragma unroll
        for (int kt = 0; kt < 8; kt++) {
            u32 ph[4], pl[4];
            u32 wa = ((const u32*)&mA)[kt >> 1];
            u32 wb = ((const u32*)&mB)[kt >> 1];
#pragma unroll
            for (int half = 0; half < 2; half++) {
                int n = 2*kt + half;
                int sh = (kt & 1)*16 + half*8 + tg*2;
                float p0 = __expf(c[n][0] * SC), p1 = __expf(c[n][1] * SC);
                float p2 = __expf(c[n][2] * SC), p3 = __expf(c[n][3] * SC);
                lsumA += p0 + p1;
                lsumB += p2 + p3;
                p0 *= ((wa >> sh) & 1)     ? INVK : 0.0f;
                p1 *= ((wa >> (sh+1)) & 1) ? INVK : 0.0f;
                p2 *= ((wb >> sh) & 1)     ? INVK : 0.0f;
                p3 *= ((wb >> (sh+1)) & 1) ? INVK : 0.0f;
                ph[2*half]     = packbf(p0, p1);
                pl[2*half]     = packlo(p0, p1, ph[2*half]);
                ph[2*half + 1] = packbf(p2, p3);
                pl[2*half + 1] = packlo(p2, p3, ph[2*half + 1]);
            }
            uint4 vb[8];
#pragma unroll
            for (int np = 0; np < 8; np++) vb[np] = ldm4(Vh + boff + np*4352 + kt*32);
            // pass 1: Ph * Vh
#pragma unroll
            for (int np = 0; np < 8; np++) {
                mma16816(o[2*np], ph[0], ph[1], ph[2], ph[3], vb[np].x, vb[np].y);
                mma16816(o[2*np+1], ph[0], ph[1], ph[2], ph[3], vb[np].z, vb[np].w);
            }
            // pass 2: Ph * Vl (inline loads)
#pragma unroll
            for (int np = 0; np < 8; np++) {
                uint4 B = ldm4(Vl + boff + np*4352 + kt*32);
                mma16816(o[2*np], ph[0], ph[1], ph[2], ph[3], B.x, B.y);
                mma16816(o[2*np+1], ph[0], ph[1], ph[2], ph[3], B.z, B.w);
            }
            // pass 3: Pl * Vh (reg-cached frags)
#pragma unroll
            for (int np = 0; np < 8; np++) {
                mma16816(o[2*np], pl[0], pl[1], pl[2], pl[3], vb[np].x, vb[np].y);
                mma16816(o[2*np+1], pl[0], pl[1], pl[2], pl[3], vb[np].z, vb[np].w);
            }
        }
        if (t < 15) CP_WAIT(0);   // K(t+1) ready
        __syncthreads();          // V buffer reuse safety
    }

    // per-row softmax denominators: reduce over quad lanes
#pragma unroll
    for (int off = 1; off <= 2; off <<= 1) {
        lsumA += __shfl_xor_sync(0xffffffffu, lsumA, off);
        lsumB += __shfl_xor_sync(0xffffffffu, lsumB, off);
    }
    const float invA = 1.0f / lsumA, invB = 1.0f / lsumB;

    float* oA = out + ((size_t)(b*SS) + q0 + w*16 + g) * HH;
    float* oB = oA + 8 * HH;
#pragma unroll
    for (int n = 0; n < 16; n++) {
        int col = n*8 + tg*2;
        *(float2*)(oA + col) = make_float2(o[n][0] * invA, o[n][1] * invA);
        *(float2*)(oB + col) = make_float2(o[n][2] * invB, o[n][3] * invB);
    }
}

extern "C" void kernel_launch(void* const* d_in, const int* in_sizes, int n_in,
                              void* d_out, int out_size)
{
    const float* x  = (const float*)d_in[0];
    const float* wq = (const float*)d_in[1];
    const float* wk = (const float*)d_in[2];
    const float* wv = (const float*)d_in[3];
    const float* du = (const float*)d_in[4];
    float* out = (float*)d_out;

    cudaFuncSetAttribute(proj_kernel, cudaFuncAttributeMaxDynamicSharedMemorySize, PROJ_SMEM);
    cudaFuncSetAttribute(attn_kernel, cudaFuncAttributeMaxDynamicSharedMemorySize, ATT_SMEM);

    xprep_kernel<<<(BB*SS*EE/4 + 255) / 256, 256>>>(x);
    wprep_kernel<<<EE*HH / 256, 256>>>(wq, wk, wv);
    maskprep_kernel<<<(int)((size_t)BB*SS*SS / 256), 256>>>(du);
    dim3 g1(BB*SS / 128, 2);
    proj_kernel<<<g1, 256, PROJ_SMEM>>>();
    dim3 g2(SS / 128, BB);
    attn_kernel<<<g2, 256, ATT_SMEM>>>(out);
}

// round 11
// speedup vs baseline: 1.0616x; 1.0177x over previous
#include <cuda_runtime.h>
#include <cuda_bf16.h>

#define BB 8
#define SS 2048
#define EE 1024
#define HH 128

typedef unsigned int u32;

// ---------------- device scratch ----------------
__device__ __nv_bfloat16 g_wth[3][HH*EE], g_wtl[3][HH*EE];   // W^T split [h][e]
__device__ __nv_bfloat16 g_qh[BB*SS*HH], g_ql[BB*SS*HH];     // Q [s][h]
__device__ __nv_bfloat16 g_kh[BB*SS*HH];                     // K hi [s][h]
__device__ __nv_bfloat16 g_vth[BB*HH*SS], g_vtl[BB*HH*SS];   // V^T [b][h][s]
__device__ u32 g_mask[BB*SS*SS/32];                          // dropout keep bits

// ---------------- helpers ----------------
__device__ __forceinline__ u32 smem_u32(const void* p) {
    u32 a;
    asm("{ .reg .u64 t; cvta.to.shared.u64 t, %1; cvt.u32.u64 %0, t; }" : "=r"(a) : "l"(p));
    return a;
}
__device__ __forceinline__ void cpa16(u32 dst, const void* src) {
    asm volatile("cp.async.cg.shared.global [%0], [%1], 16;" :: "r"(dst), "l"(src));
}
#define CP_COMMIT() asm volatile("cp.async.commit_group;" ::: "memory")
#define CP_WAIT(n)  asm volatile("cp.async.wait_group %0;" :: "n"(n) : "memory")

__device__ __forceinline__ u32 packbf(float lo, float hi) {
    u32 r;
    asm("cvt.rn.bf16x2.f32 %0, %1, %2;" : "=r"(r) : "f"(hi), "f"(lo));
    return r;
}
__device__ __forceinline__ u32 packlo(float p0, float p1, u32 h) {
    float r0 = p0 - __uint_as_float(h << 16);
    float r1 = p1 - __uint_as_float(h & 0xffff0000u);
    return packbf(r0, r1);
}
__device__ __forceinline__ void mma16816(float* c, u32 a0, u32 a1, u32 a2, u32 a3,
                                         u32 b0, u32 b1) {
    asm volatile("mma.sync.aligned.m16n8k16.row.col.f32.bf16.bf16.f32 "
                 "{%0,%1,%2,%3},{%4,%5,%6,%7},{%8,%9},{%0,%1,%2,%3};"
                 : "+f"(c[0]), "+f"(c[1]), "+f"(c[2]), "+f"(c[3])
                 : "r"(a0), "r"(a1), "r"(a2), "r"(a3), "r"(b0), "r"(b1));
}
__device__ __forceinline__ void mmaA(float* c, const uint4& a, u32 b0, u32 b1) {
    mma16816(c, a.x, a.y, a.z, a.w, b0, b1);
}
__device__ __forceinline__ uint4 ldm4(u32 addr) {
    uint4 r;
    asm volatile("ldmatrix.sync.aligned.m8n8.x4.shared.b16 {%0,%1,%2,%3}, [%4];"
                 : "=r"(r.x), "=r"(r.y), "=r"(r.z), "=r"(r.w) : "r"(addr));
    return r;
}

// ---------------------------------------------------------------------------
// prep kernels
// ---------------------------------------------------------------------------
__global__ __launch_bounds__(256) void wprep_kernel(
    const float* __restrict__ wq, const float* __restrict__ wk,
    const float* __restrict__ wv)
{
    int idx = blockIdx.x * 256 + threadIdx.x;   // e*128+h
    int e = idx >> 7, h = idx & 127;
    int o = h * EE + e;
    const float* src[3] = {wq, wk, wv};
#pragma unroll
    for (int m = 0; m < 3; m++) {
        float v = src[m][idx];
        __nv_bfloat16 hi = __float2bfloat16_rn(v);
        g_wth[m][o] = hi;
        g_wtl[m][o] = __float2bfloat16_rn(v - __bfloat162float(hi));
    }
}
__global__ __launch_bounds__(256) void maskprep_kernel(const float* __restrict__ du) {
    size_t gid = (size_t)blockIdx.x * 256 + threadIdx.x;
    u32 m = __ballot_sync(0xffffffffu, du[gid] >= 0.1f);
    if ((threadIdx.x & 31) == 0) g_mask[gid >> 5] = m;
}

// ---------------------------------------------------------------------------
// proj: 256 threads, 8 warps, warp tile M=64 x N=32.
// blockIdx.y==0: merged q+k CTA (2-pass each, shares X A-frags).
// blockIdx.y==1: v CTA (3-pass) with transposed V^T store.
// X is read as raw f32 one chunk ahead (LDG into regs), converted to bf16
// hi(/lo) in-kernel, STS'd into the next stage's X tile — no xprep kernel.
// W tiles via cp.async 2-stage. Tiles [128][72] bf16 (144B pitch).
// qk stage = {Xh, Wqh, Wql, Wkh, Wkl}; v stage = {Xh, Xl, Wvh, Wvl}.
// ---------------------------------------------------------------------------
#define PJ_T 18432            // 128*72*2
#define PROJ_SMEM (2 * 5 * PJ_T)   // 184320

__device__ __forceinline__ void chunk_load(u32 dst, const __nv_bfloat16* src) {
    int tid = threadIdx.x;
#pragma unroll
    for (int i = 0; i < 4; i++) {
        int id = tid + i * 256;
        int r = id >> 3, q = id & 7;
        cpa16(dst + r * 144 + q * 16, (const char*)src + (size_t)r * 2048 + q * 16);
    }
}
// per-thread: 32 f32 of X (row r, cols half*32..+31 of the 64-wide chunk)
__device__ __forceinline__ void ldg_x(float4* xr, const float* __restrict__ x,
                                      int row0, int e0, int r, int half) {
    const float4* s = (const float4*)(x + (size_t)(row0 + r) * EE + e0 + half * 32);
#pragma unroll
    for (int i = 0; i < 8; i++) xr[i] = s[i];
}
__device__ __forceinline__ void conv_store_hi(char* xh_tile, const float4* xr,
                                              int r, int half) {
    const float* f = (const float*)xr;
    u32 h[16];
#pragma unroll
    for (int j = 0; j < 16; j++) h[j] = packbf(f[2*j], f[2*j+1]);
    char* p = xh_tile + r * 144 + half * 64;
#pragma unroll
    for (int q = 0; q < 4; q++)
        *(uint4*)(p + q*16) = make_uint4(h[4*q], h[4*q+1], h[4*q+2], h[4*q+3]);
}
__device__ __forceinline__ void conv_store_hilo(char* xh_tile, char* xl_tile,
                                                const float4* xr, int r, int half) {
    const float* f = (const float*)xr;
    u32 h[16], l[16];
#pragma unroll
    for (int j = 0; j < 16; j++) {
        h[j] = packbf(f[2*j], f[2*j+1]);
        l[j] = packlo(f[2*j], f[2*j+1], h[j]);
    }
    char* p = xh_tile + r * 144 + half * 64;
    char* q2 = xl_tile + r * 144 + half * 64;
#pragma unroll
    for (int q = 0; q < 4; q++) {
        *(uint4*)(p + q*16)  = make_uint4(h[4*q], h[4*q+1], h[4*q+2], h[4*q+3]);
        *(uint4*)(q2 + q*16) = make_uint4(l[4*q], l[4*q+1], l[4*q+2], l[4*q+3]);
    }
}

__global__ __launch_bounds__(256) void proj_kernel(const float* __restrict__ x) {
    extern __shared__ char sm[];
    const u32 sb = smem_u32(sm);
    const int tid = threadIdx.x, w = tid >> 5, lane = tid & 31;
    const int wy = w >> 2, wx = w & 3;
    const int g = lane >> 2, tg = lane & 3;
    const int row0 = blockIdx.x * 128;
    const bool isqk = (blockIdx.y == 0);
    const int xr_r = tid >> 1, xr_half = tid & 1;

    const u32 aoff = (u32)((wy*64 + (lane & 15)) * 144 + ((lane >> 4) & 1) * 16);
    const u32 boff = (u32)((wx*32 + (lane & 7) + ((lane >> 4) & 1) * 8) * 144
                           + ((lane >> 3) & 1) * 16);

    float c0[16][4], c1[16][4];
#pragma unroll
    for (int n = 0; n < 16; n++)
#pragma unroll
        for (int j = 0; j < 4; j++) { c0[n][j] = 0.0f; c1[n][j] = 0.0f; }

    const u32 STG = (isqk ? 5u : 4u) * PJ_T;

    float4 xr[8];
    // chunk 0: X via LDG+convert (latency exposed once), W via cp.async
    ldg_x(xr, x, row0, 0, xr_r, xr_half);
    if (isqk) {
        conv_store_hi(sm, xr, xr_r, xr_half);
        chunk_load(sb + PJ_T,   g_wth[0]);
        chunk_load(sb + 2*PJ_T, g_wtl[0]);
        chunk_load(sb + 3*PJ_T, g_wth[1]);
        chunk_load(sb + 4*PJ_T, g_wtl[1]);
    } else {
        conv_store_hilo(sm, sm + PJ_T, xr, xr_r, xr_half);
        chunk_load(sb + 2*PJ_T, g_wth[2]);
        chunk_load(sb + 3*PJ_T, g_wtl[2]);
    }
    CP_COMMIT();
    ldg_x(xr, x, row0, 64, xr_r, xr_half);   // prefetch chunk 1

    for (int ch = 0; ch < 16; ch++) {
        int cur = ch & 1;
        if (ch < 15) {
            char* np = sm + (cur ^ 1) * STG;
            u32 nb = sb + (cur ^ 1) * STG;
            int o = (ch + 1) * 64;
            if (isqk) {
                chunk_load(nb + PJ_T,   g_wth[0] + o);
                chunk_load(nb + 2*PJ_T, g_wtl[0] + o);
                chunk_load(nb + 3*PJ_T, g_wth[1] + o);
                chunk_load(nb + 4*PJ_T, g_wtl[1] + o);
            } else {
                chunk_load(nb + 2*PJ_T, g_wth[2] + o);
                chunk_load(nb + 3*PJ_T, g_wtl[2] + o);
            }
            CP_COMMIT();
            // convert+store X(ch+1) into next buffer (prev trailing sync makes it safe)
            if (isqk) conv_store_hi(np, xr, xr_r, xr_half);
            else      conv_store_hilo(np, np + PJ_T, xr, xr_r, xr_half);
            if (ch < 14) ldg_x(xr, x, row0, (ch + 2) * 64, xr_r, xr_half);
            CP_WAIT(1);
        } else {
            CP_WAIT(0);
        }
        __syncthreads();
        const u32 base = sb + cur * STG;

        if (isqk) {
#pragma unroll
            for (int kt = 0; kt < 4; kt++) {
                uint4 A[4];
#pragma unroll
                for (int mf = 0; mf < 4; mf++)
                    A[mf] = ldm4(base + aoff + mf*2304 + kt*32);
                // pass: q hi
                {
                    uint4 B0 = ldm4(base + PJ_T + boff + kt*32);
                    uint4 B1 = ldm4(base + PJ_T + boff + 2304 + kt*32);
#pragma unroll
                    for (int mf = 0; mf < 4; mf++) {
                        mmaA(c0[mf*4+0], A[mf], B0.x, B0.y);
                        mmaA(c0[mf*4+1], A[mf], B0.z, B0.w);
                        mmaA(c0[mf*4+2], A[mf], B1.x, B1.y);
                        mmaA(c0[mf*4+3], A[mf], B1.z, B1.w);
                    }
                }
                // pass: k hi
                {
                    uint4 B0 = ldm4(base + 3*PJ_T + boff + kt*32);
                    uint4 B1 = ldm4(base + 3*PJ_T + boff + 2304 + kt*32);
#pragma unroll
                    for (int mf = 0; mf < 4; mf++) {
                        mmaA(c1[mf*4+0], A[mf], B0.x, B0.y);
                        mmaA(c1[mf*4+1], A[mf], B0.z, B0.w);
                        mmaA(c1[mf*4+2], A[mf], B1.x, B1.y);
                        mmaA(c1[mf*4+3], A[mf], B1.z, B1.w);
                    }
                }
                // pass: q lo
                {
                    uint4 B0 = ldm4(base + 2*PJ_T + boff + kt*32);
                    uint4 B1 = ldm4(base + 2*PJ_T + boff + 2304 + kt*32);
#pragma unroll
                    for (int mf = 0; mf < 4; mf++) {
                        mmaA(c0[mf*4+0], A[mf], B0.x, B0.y);
                        mmaA(c0[mf*4+1], A[mf], B0.z, B0.w);
                        mmaA(c0[mf*4+2], A[mf], B1.x, B1.y);
                        mmaA(c0[mf*4+3], A[mf], B1.z, B1.w);
                    }
                }
                // pass: k lo
                {
                    uint4 B0 = ldm4(base + 4*PJ_T + boff + kt*32);
                    uint4 B1 = ldm4(base + 4*PJ_T + boff + 2304 + kt*32);
#pragma unroll
                    for (int mf = 0; mf < 4; mf++) {
                        mmaA(c1[mf*4+0], A[mf], B0.x, B0.y);
                        mmaA(c1[mf*4+1], A[mf], B0.z, B0.w);
                        mmaA(c1[mf*4+2], A[mf], B1.x, B1.y);
                        mmaA(c1[mf*4+3], A[mf], B1.z, B1.w);
                    }
                }
            }
        } else {
#pragma unroll
            for (int kt = 0; kt < 4; kt++) {
                uint4 A[4], AL[4];
#pragma unroll
                for (int mf = 0; mf < 4; mf++) {
                    A[mf]  = ldm4(base + aoff + mf*2304 + kt*32);
                    AL[mf] = ldm4(base + PJ_T + aoff + mf*2304 + kt*32);
                }
                uint4 Bh0 = ldm4(base + 2*PJ_T + boff + kt*32);
                uint4 Bh1 = ldm4(base + 2*PJ_T + boff + 2304 + kt*32);
                uint4 Bl0 = ldm4(base + 3*PJ_T + boff + kt*32);
                uint4 Bl1 = ldm4(base + 3*PJ_T + boff + 2304 + kt*32);
                // pass 1: Xh * Wh
#pragma unroll
                for (int mf = 0; mf < 4; mf++) {
                    mmaA(c0[mf*4+0], A[mf], Bh0.x, Bh0.y);
                    mmaA(c0[mf*4+1], A[mf], Bh0.z, Bh0.w);
                    mmaA(c0[mf*4+2], A[mf], Bh1.x, Bh1.y);
                    mmaA(c0[mf*4+3], A[mf], Bh1.z, Bh1.w);
                }
                // pass 2: Xh * Wl
#pragma unroll
                for (int mf = 0; mf < 4; mf++) {
                    mmaA(c0[mf*4+0], A[mf], Bl0.x, Bl0.y);
                    mmaA(c0[mf*4+1], A[mf], Bl0.z, Bl0.w);
                    mmaA(c0[mf*4+2], A[mf], Bl1.x, Bl1.y);
                    mmaA(c0[mf*4+3], A[mf], Bl1.z, Bl1.w);
                }
                // pass 3: Xl * Wh
#pragma unroll
                for (int mf = 0; mf < 4; mf++) {
                    mmaA(c0[mf*4+0], AL[mf], Bh0.x, Bh0.y);
                    mmaA(c0[mf*4+1], AL[mf], Bh0.z, Bh0.w);
                    mmaA(c0[mf*4+2], AL[mf], Bh1.x, Bh1.y);
                    mmaA(c0[mf*4+3], AL[mf], Bh1.z, Bh1.w);
                }
            }
        }
        __syncthreads();
    }

    if (isqk) {
#pragma unroll
        for (int mf = 0; mf < 4; mf++) {
            size_t rA = (size_t)(row0 + wy*64 + mf*16 + g) * HH;
            size_t rB = rA + 8 * HH;
#pragma unroll
            for (int f = 0; f < 4; f++) {
                int col = wx*32 + (f >> 1)*16 + (f & 1)*8 + tg*2;
                const float* cq = c0[mf*4 + f];
                const float* ck = c1[mf*4 + f];
                u32 qh0 = packbf(cq[0], cq[1]);
                u32 qh1 = packbf(cq[2], cq[3]);
                *(u32*)&g_qh[rA + col] = qh0;
                *(u32*)&g_qh[rB + col] = qh1;
                *(u32*)&g_ql[rA + col] = packlo(cq[0], cq[1], qh0);
                *(u32*)&g_ql[rB + col] = packlo(cq[2], cq[3], qh1);
                *(u32*)&g_kh[rA + col] = packbf(ck[0], ck[1]);
                *(u32*)&g_kh[rB + col] = packbf(ck[2], ck[3]);
            }
        }
    } else {
        float* Cs = (float*)sm;   // [128][132] f32 staging for transpose
#pragma unroll
        for (int mf = 0; mf < 4; mf++) {
            int r = wy*64 + mf*16 + g;
#pragma unroll
            for (int f = 0; f < 4; f++) {
                int col = wx*32 + (f >> 1)*16 + (f & 1)*8 + tg*2;
                const float* cv = c0[mf*4 + f];
                Cs[r * 132 + col]           = cv[0];
                Cs[r * 132 + col + 1]       = cv[1];
                Cs[(r + 8) * 132 + col]     = cv[2];
                Cs[(r + 8) * 132 + col + 1] = cv[3];
            }
        }
        __syncthreads();
        int h = tid >> 1, half = tid & 1;
        int b = row0 >> 11, s0 = row0 & 2047;
        union { __nv_bfloat16 v[64]; uint4 u[8]; } Hh, Ll;
#pragma unroll
        for (int j = 0; j < 64; j++) {
            float f = Cs[(half*64 + j) * 132 + h];
            __nv_bfloat16 hi = __float2bfloat16_rn(f);
            Hh.v[j] = hi;
            Ll.v[j] = __float2bfloat16_rn(f - __bfloat162float(hi));
        }
        size_t ob = ((size_t)(b*HH + h)) * SS + s0 + half*64;
#pragma unroll
        for (int j = 0; j < 8; j++) {
            *(uint4*)&g_vth[ob + j*8] = Hh.u[j];
            *(uint4*)&g_vtl[ob + j*8] = Ll.u[j];
        }
    }
}

// ---------------------------------------------------------------------------
// attn: CTA = 128 Q rows x one batch. 8 warps, warp = 16 rows.
// QK 2-pass with K frags reg-cached; PV 3-pass with Vh frags reg-cached.
// Dropout via prepacked bitmask. smem: Qh,Ql,Kh,Vth,Vtl [128][136] (272B pitch).
// ---------------------------------------------------------------------------
#define AT_T 34816            // 128*136*2
#define ATT_SMEM (5 * AT_T)

__device__ __forceinline__ void tile_load(u32 dst, const __nv_bfloat16* src,
                                          int stride_elems) {
    int tid = threadIdx.x;
#pragma unroll
    for (int i = 0; i < 8; i++) {
        int id = tid + i * 256;
        int r = id >> 4, q = id & 15;
        cpa16(dst + r * 272 + q * 16,
              (const char*)src + (size_t)r * stride_elems * 2 + q * 16);
    }
}

__global__ __launch_bounds__(256) void attn_kernel(float* __restrict__ out)
{
    extern __shared__ char sm[];
    const u32 sb = smem_u32(sm);
    const int tid = threadIdx.x, w = tid >> 5, lane = tid & 31;
    const int g = lane >> 2, tg = lane & 3;
    const int b = blockIdx.y;
    const int q0 = blockIdx.x * 128;

    const u32 Qh = sb, Ql = sb + AT_T, Kh = sb + 2*AT_T;
    const u32 Vh = sb + 3*AT_T, Vl = sb + 4*AT_T;

    const u32 aoff = (u32)((w*16 + (lane & 15)) * 272 + ((lane >> 4) & 1) * 16);
    const u32 boff = (u32)(((lane & 7) + ((lane >> 4) & 1) * 8) * 272 + ((lane >> 3) & 1) * 16);

    const size_t qoff = (size_t)(b*SS + q0) * HH;
    tile_load(Qh, g_qh + qoff, HH);
    tile_load(Ql, g_ql + qoff, HH);
    tile_load(Kh, g_kh + (size_t)(b*SS) * HH, HH);
    CP_COMMIT();

    float o[16][4];
#pragma unroll
    for (int n = 0; n < 16; n++)
#pragma unroll
        for (int j = 0; j < 4; j++) o[n][j] = 0.0f;
    float lsumA = 0.0f, lsumB = 0.0f;

    const float SC = 0.03125f;        // 1024^-0.5
    const float INVK = 1.0f / 0.9f;
    const u32* mrowA = g_mask + ((size_t)(b*SS) + q0 + w*16 + g) * (SS/32);
    const u32* mrowB = mrowA + 8 * (SS/32);

    CP_WAIT(0);
    __syncthreads();

    for (int t = 0; t < 16; t++) {
        const int k0 = t * 128;
        // V(t) load overlaps QK(t)
        tile_load(Vh, g_vth + (size_t)(b*HH) * SS + k0, SS);
        tile_load(Vl, g_vtl + (size_t)(b*HH) * SS + k0, SS);
        CP_COMMIT();
        uint4 mA = *(const uint4*)(mrowA + t*4);
        uint4 mB = *(const uint4*)(mrowB + t*4);

        float c[16][4];
#pragma unroll
        for (int n = 0; n < 16; n++)
#pragma unroll
            for (int j = 0; j < 4; j++) c[n][j] = 0.0f;

#pragma unroll
        for (int kt = 0; kt < 8; kt++) {
            uint4 AH = ldm4(Qh + aoff + kt*32);
            uint4 AL = ldm4(Ql + aoff + kt*32);
            uint4 kb[8];
#pragma unroll
            for (int np = 0; np < 8; np++) kb[np] = ldm4(Kh + boff + np*4352 + kt*32);
            // pass 1: Qh * Kh
#pragma unroll
            for (int np = 0; np < 8; np++) {
                mmaA(c[2*np], AH, kb[np].x, kb[np].y);
                mmaA(c[2*np+1], AH, kb[np].z, kb[np].w);
            }
            // pass 2: Ql * Kh (reg-cached frags)
#pragma unroll
            for (int np = 0; np < 8; np++) {
                mmaA(c[2*np], AL, kb[np].x, kb[np].y);
                mmaA(c[2*np+1], AL, kb[np].z, kb[np].w);
            }
        }

        CP_WAIT(0);          // V(t) ready
        __syncthreads();     // all warps done reading K(t)
        if (t < 15) {
            tile_load(Kh, g_kh + (size_t)(b*SS + k0 + 128) * HH, HH);
            CP_COMMIT();
        }

        // softmax + dropout(numerator only) + PV
#pragma unroll
        for (int kt = 0; kt < 8; kt++) {
            u32 ph[4], pl[4];
            u32 wa = ((const u32*)&mA)[kt >> 1];
            u32 wb = ((const u32*)&mB)[kt >> 1];
#pragma unroll
            for (int half = 0; half < 2; half++) {
                int n = 2*kt + half;
                int sh = (kt & 1)*16 + half*8 + tg*2;
                float p0 = __expf(c[n][0] * SC), p1 = __expf(c[n][1] * SC);
                float p2 = __expf(c[n][2] * SC), p3 = __expf(c[n][3] * SC);
                lsumA += p0 + p1;
                lsumB += p2 + p3;
                p0 *= ((wa >> sh) & 1)     ? INVK : 0.0f;
                p1 *= ((wa >> (sh+1)) & 1) ? INVK : 0.0f;
                p2 *= ((wb >> sh) & 1)     ? INVK : 0.0f;
                p3 *= ((wb >> (sh+1)) & 1) ? INVK : 0.0f;
                ph[2*half]     = packbf(p0, p1);
                pl[2*half]     = packlo(p0, p1, ph[2*half]);
                ph[2*half + 1] = packbf(p2, p3);
                pl[2*half + 1] = packlo(p2, p3, ph[2*half + 1]);
            }
            uint4 vb[8];
#pragma unroll
            for (int np = 0; np < 8; np++) vb[np] = ldm4(Vh + boff + np*4352 + kt*32);
            // pass 1: Ph * Vh
#pragma unroll
            for (int np = 0; np < 8; np++) {
                mma16816(o[2*np], ph[0], ph[1], ph[2], ph[3], vb[np].x, vb[np].y);
                mma16816(o[2*np+1], ph[0], ph[1], ph[2], ph[3], vb[np].z, vb[np].w);
            }
            // pass 2: Ph * Vl (inline loads)
#pragma unroll
            for (int np = 0; np < 8; np++) {
                uint4 B = ldm4(Vl + boff + np*4352 + kt*32);
                mma16816(o[2*np], ph[0], ph[1], ph[2], ph[3], B.x, B.y);
                mma16816(o[2*np+1], ph[0], ph[1], ph[2], ph[3], B.z, B.w);
            }
            // pass 3: Pl * Vh (reg-cached frags)
#pragma unroll
            for (int np = 0; np < 8; np++) {
                mma16816(o[2*np], pl[0], pl[1], pl[2], pl[3], vb[np].x, vb[np].y);
                mma16816(o[2*np+1], pl[0], pl[1], pl[2], pl[3], vb[np].z, vb[np].w);
            }
        }
        if (t < 15) CP_WAIT(0);   // K(t+1) ready
        __syncthreads();          // V buffer reuse safety
    }

    // per-row softmax denominators: reduce over quad lanes
#pragma unroll
    for (int off = 1; off <= 2; off <<= 1) {
        lsumA += __shfl_xor_sync(0xffffffffu, lsumA, off);
        lsumB += __shfl_xor_sync(0xffffffffu, lsumB, off);
    }
    const float invA = 1.0f / lsumA, invB = 1.0f / lsumB;

    float* oA = out + ((size_t)(b*SS) + q0 + w*16 + g) * HH;
    float* oB = oA + 8 * HH;
#pragma unroll
    for (int n = 0; n < 16; n++) {
        int col = n*8 + tg*2;
        *(float2*)(oA + col) = make_float2(o[n][0] * invA, o[n][1] * invA);
        *(float2*)(oB + col) = make_float2(o[n][2] * invB, o[n][3] * invB);
    }
}

extern "C" void kernel_launch(void* const* d_in, const int* in_sizes, int n_in,
                              void* d_out, int out_size)
{
    const float* x  = (const float*)d_in[0];
    const float* wq = (const float*)d_in[1];
    const float* wk = (const float*)d_in[2];
    const float* wv = (const float*)d_in[3];
    const float* du = (const float*)d_in[4];
    float* out = (float*)d_out;

    cudaFuncSetAttribute(proj_kernel, cudaFuncAttributeMaxDynamicSharedMemorySize, PROJ_SMEM);
    cudaFuncSetAttribute(attn_kernel, cudaFuncAttributeMaxDynamicSharedMemorySize, ATT_SMEM);

    wprep_kernel<<<EE*HH / 256, 256>>>(wq, wk, wv);
    maskprep_kernel<<<(int)((size_t)BB*SS*SS / 256), 256>>>(du);
    dim3 g1(BB*SS / 128, 2);
    proj_kernel<<<g1, 256, PROJ_SMEM>>>(x);
    dim3 g2(SS / 128, BB);
    attn_kernel<<<g2, 256, ATT_SMEM>>>(out);
}

// round 12
// speedup vs baseline: 1.3367x; 1.2592x over previous
#include <cuda_runtime.h>
#include <cuda_bf16.h>

#define BB 8
#define SS 2048
#define EE 1024
#define HH 128

typedef unsigned int u32;

// ---------------- device scratch ----------------
__device__ __nv_bfloat16 g_wth[3][HH*EE], g_wtl[3][HH*EE];   // W^T split [h][e]
__device__ __nv_bfloat16 g_qh[BB*SS*HH], g_ql[BB*SS*HH];     // Q [s][h]
__device__ __nv_bfloat16 g_kh[BB*SS*HH];                     // K hi [s][h]
__device__ __nv_bfloat16 g_vth[BB*HH*SS], g_vtl[BB*HH*SS];   // V^T [b][h][s]

// ---------------- helpers ----------------
__device__ __forceinline__ u32 smem_u32(const void* p) {
    u32 a;
    asm("{ .reg .u64 t; cvta.to.shared.u64 t, %1; cvt.u32.u64 %0, t; }" : "=r"(a) : "l"(p));
    return a;
}
__device__ __forceinline__ void cpa16(u32 dst, const void* src) {
    asm volatile("cp.async.cg.shared.global [%0], [%1], 16;" :: "r"(dst), "l"(src));
}
#define CP_COMMIT() asm volatile("cp.async.commit_group;" ::: "memory")
#define CP_WAIT(n)  asm volatile("cp.async.wait_group %0;" :: "n"(n) : "memory")

__device__ __forceinline__ u32 packbf(float lo, float hi) {
    u32 r;
    asm("cvt.rn.bf16x2.f32 %0, %1, %2;" : "=r"(r) : "f"(hi), "f"(lo));
    return r;
}
__device__ __forceinline__ u32 packlo(float p0, float p1, u32 h) {
    float r0 = p0 - __uint_as_float(h << 16);
    float r1 = p1 - __uint_as_float(h & 0xffff0000u);
    return packbf(r0, r1);
}
__device__ __forceinline__ void mma16816(float* c, u32 a0, u32 a1, u32 a2, u32 a3,
                                         u32 b0, u32 b1) {
    asm volatile("mma.sync.aligned.m16n8k16.row.col.f32.bf16.bf16.f32 "
                 "{%0,%1,%2,%3},{%4,%5,%6,%7},{%8,%9},{%0,%1,%2,%3};"
                 : "+f"(c[0]), "+f"(c[1]), "+f"(c[2]), "+f"(c[3])
                 : "r"(a0), "r"(a1), "r"(a2), "r"(a3), "r"(b0), "r"(b1));
}
__device__ __forceinline__ void mmaA(float* c, const uint4& a, u32 b0, u32 b1) {
    mma16816(c, a.x, a.y, a.z, a.w, b0, b1);
}
__device__ __forceinline__ uint4 ldm4(u32 addr) {
    uint4 r;
    asm volatile("ldmatrix.sync.aligned.m8n8.x4.shared.b16 {%0,%1,%2,%3}, [%4];"
                 : "=r"(r.x), "=r"(r.y), "=r"(r.z), "=r"(r.w) : "r"(addr));
    return r;
}

// ---------------------------------------------------------------------------
// wprep: W [E][H] f32 -> W^T [H][E] hi/lo bf16, smem-tiled transpose.
// grid 48 = 3 matrices x 16 e-chunks of 64. Coalesced reads AND writes.
// ---------------------------------------------------------------------------
__global__ __launch_bounds__(256) void wprep_kernel(
    const float* __restrict__ wq, const float* __restrict__ wk,
    const float* __restrict__ wv)
{
    __shared__ float Ws[64][132];
    const int m = blockIdx.x >> 4, chunk = blockIdx.x & 15;
    const float* __restrict__ src = (m == 0) ? wq : (m == 1) ? wk : wv;
    const int e0 = chunk * 64;
    const int tid = threadIdx.x;

    // load 64 e-rows x 128 h-cols, coalesced float4
#pragma unroll
    for (int i = 0; i < 8; i++) {
        int id = tid + i * 256;
        int e = id >> 5, hc = (id & 31) * 4;
        *(float4*)&Ws[e][hc] = *(const float4*)&src[(size_t)(e0 + e) * HH + hc];
    }
    __syncthreads();

    // write transposed: thread = (h, 32-wide e half), coalesced 64B stores
    const int h = tid >> 1, eh = (tid & 1) * 32;
    union { __nv_bfloat16 v[32]; uint4 u[4]; } Hh, Ll;
#pragma unroll
    for (int j = 0; j < 32; j++) {
        float f = Ws[eh + j][h];
        __nv_bfloat16 hi = __float2bfloat16_rn(f);
        Hh.v[j] = hi;
        Ll.v[j] = __float2bfloat16_rn(f - __bfloat162float(hi));
    }
    size_t ob = (size_t)h * EE + e0 + eh;
#pragma unroll
    for (int j = 0; j < 4; j++) {
        *(uint4*)&g_wth[m][ob + j*8] = Hh.u[j];
        *(uint4*)&g_wtl[m][ob + j*8] = Ll.u[j];
    }
}

// ---------------------------------------------------------------------------
// proj: 256 threads, 8 warps, warp tile M=64 x N=32.
// blockIdx.y==0: merged q+k CTA (2-pass each, shares X A-frags).
// blockIdx.y==1: v CTA (3-pass) with transposed V^T store.
// X read as raw f32 one chunk ahead (LDG into regs), converted to bf16 in-
// kernel, STS'd into the next stage's X tile. W via cp.async 2-stage.
// Tiles [128][72] bf16 (144B pitch).
// ---------------------------------------------------------------------------
#define PJ_T 18432            // 128*72*2
#define PROJ_SMEM (2 * 5 * PJ_T)   // 184320

__device__ __forceinline__ void chunk_load(u32 dst, const __nv_bfloat16* src) {
    int tid = threadIdx.x;
#pragma unroll
    for (int i = 0; i < 4; i++) {
        int id = tid + i * 256;
        int r = id >> 3, q = id & 7;
        cpa16(dst + r * 144 + q * 16, (const char*)src + (size_t)r * 2048 + q * 16);
    }
}
__device__ __forceinline__ void ldg_x(float4* xr, const float* __restrict__ x,
                                      int row0, int e0, int r, int half) {
    const float4* s = (const float4*)(x + (size_t)(row0 + r) * EE + e0 + half * 32);
#pragma unroll
    for (int i = 0; i < 8; i++) xr[i] = s[i];
}
__device__ __forceinline__ void conv_store_hi(char* xh_tile, const float4* xr,
                                              int r, int half) {
    const float* f = (const float*)xr;
    u32 h[16];
#pragma unroll
    for (int j = 0; j < 16; j++) h[j] = packbf(f[2*j], f[2*j+1]);
    char* p = xh_tile + r * 144 + half * 64;
#pragma unroll
    for (int q = 0; q < 4; q++)
        *(uint4*)(p + q*16) = make_uint4(h[4*q], h[4*q+1], h[4*q+2], h[4*q+3]);
}
__device__ __forceinline__ void conv_store_hilo(char* xh_tile, char* xl_tile,
                                                const float4* xr, int r, int half) {
    const float* f = (const float*)xr;
    u32 h[16], l[16];
#pragma unroll
    for (int j = 0; j < 16; j++) {
        h[j] = packbf(f[2*j], f[2*j+1]);
        l[j] = packlo(f[2*j], f[2*j+1], h[j]);
    }
    char* p = xh_tile + r * 144 + half * 64;
    char* q2 = xl_tile + r * 144 + half * 64;
#pragma unroll
    for (int q = 0; q < 4; q++) {
        *(uint4*)(p + q*16)  = make_uint4(h[4*q], h[4*q+1], h[4*q+2], h[4*q+3]);
        *(uint4*)(q2 + q*16) = make_uint4(l[4*q], l[4*q+1], l[4*q+2], l[4*q+3]);
    }
}

__global__ __launch_bounds__(256) void proj_kernel(const float* __restrict__ x) {
    extern __shared__ char sm[];
    const u32 sb = smem_u32(sm);
    const int tid = threadIdx.x, w = tid >> 5, lane = tid & 31;
    const int wy = w >> 2, wx = w & 3;
    const int g = lane >> 2, tg = lane & 3;
    const int row0 = blockIdx.x * 128;
    const bool isqk = (blockIdx.y == 0);
    const int xr_r = tid >> 1, xr_half = tid & 1;

    const u32 aoff = (u32)((wy*64 + (lane & 15)) * 144 + ((lane >> 4) & 1) * 16);
    const u32 boff = (u32)((wx*32 + (lane & 7) + ((lane >> 4) & 1) * 8) * 144
                           + ((lane >> 3) & 1) * 16);

    float c0[16][4], c1[16][4];
#pragma unroll
    for (int n = 0; n < 16; n++)
#pragma unroll
        for (int j = 0; j < 4; j++) { c0[n][j] = 0.0f; c1[n][j] = 0.0f; }

    const u32 STG = (isqk ? 5u : 4u) * PJ_T;

    float4 xr[8];
    ldg_x(xr, x, row0, 0, xr_r, xr_half);
    if (isqk) {
        conv_store_hi(sm, xr, xr_r, xr_half);
        chunk_load(sb + PJ_T,   g_wth[0]);
        chunk_load(sb + 2*PJ_T, g_wtl[0]);
        chunk_load(sb + 3*PJ_T, g_wth[1]);
        chunk_load(sb + 4*PJ_T, g_wtl[1]);
    } else {
        conv_store_hilo(sm, sm + PJ_T, xr, xr_r, xr_half);
        chunk_load(sb + 2*PJ_T, g_wth[2]);
        chunk_load(sb + 3*PJ_T, g_wtl[2]);
    }
    CP_COMMIT();
    ldg_x(xr, x, row0, 64, xr_r, xr_half);

    for (int ch = 0; ch < 16; ch++) {
        int cur = ch & 1;
        if (ch < 15) {
            char* np = sm + (cur ^ 1) * STG;
            u32 nb = sb + (cur ^ 1) * STG;
            int o = (ch + 1) * 64;
            if (isqk) {
                chunk_load(nb + PJ_T,   g_wth[0] + o);
                chunk_load(nb + 2*PJ_T, g_wtl[0] + o);
                chunk_load(nb + 3*PJ_T, g_wth[1] + o);
                chunk_load(nb + 4*PJ_T, g_wtl[1] + o);
            } else {
                chunk_load(nb + 2*PJ_T, g_wth[2] + o);
                chunk_load(nb + 3*PJ_T, g_wtl[2] + o);
            }
            CP_COMMIT();
            if (isqk) conv_store_hi(np, xr, xr_r, xr_half);
            else      conv_store_hilo(np, np + PJ_T, xr, xr_r, xr_half);
            if (ch < 14) ldg_x(xr, x, row0, (ch + 2) * 64, xr_r, xr_half);
            CP_WAIT(1);
        } else {
            CP_WAIT(0);
        }
        __syncthreads();
        const u32 base = sb + cur * STG;

        if (isqk) {
#pragma unroll
            for (int kt = 0; kt < 4; kt++) {
                uint4 A[4];
#pragma unroll
                for (int mf = 0; mf < 4; mf++)
                    A[mf] = ldm4(base + aoff + mf*2304 + kt*32);
                // pass: q hi
                {
                    uint4 B0 = ldm4(base + PJ_T + boff + kt*32);
                    uint4 B1 = ldm4(base + PJ_T + boff + 2304 + kt*32);
#pragma unroll
                    for (int mf = 0; mf < 4; mf++) {
                        mmaA(c0[mf*4+0], A[mf], B0.x, B0.y);
                        mmaA(c0[mf*4+1], A[mf], B0.z, B0.w);
                        mmaA(c0[mf*4+2], A[mf], B1.x, B1.y);
                        mmaA(c0[mf*4+3], A[mf], B1.z, B1.w);
                    }
                }
                // pass: k hi
                {
                    uint4 B0 = ldm4(base + 3*PJ_T + boff + kt*32);
                    uint4 B1 = ldm4(base + 3*PJ_T + boff + 2304 + kt*32);
#pragma unroll
                    for (int mf = 0; mf < 4; mf++) {
                        mmaA(c1[mf*4+0], A[mf], B0.x, B0.y);
                        mmaA(c1[mf*4+1], A[mf], B0.z, B0.w);
                        mmaA(c1[mf*4+2], A[mf], B1.x, B1.y);
                        mmaA(c1[mf*4+3], A[mf], B1.z, B1.w);
                    }
                }
                // pass: q lo
                {
                    uint4 B0 = ldm4(base + 2*PJ_T + boff + kt*32);
                    uint4 B1 = ldm4(base + 2*PJ_T + boff + 2304 + kt*32);
#pragma unroll
                    for (int mf = 0; mf < 4; mf++) {
                        mmaA(c0[mf*4+0], A[mf], B0.x, B0.y);
                        mmaA(c0[mf*4+1], A[mf], B0.z, B0.w);
                        mmaA(c0[mf*4+2], A[mf], B1.x, B1.y);
                        mmaA(c0[mf*4+3], A[mf], B1.z, B1.w);
                    }
                }
                // pass: k lo
                {
                    uint4 B0 = ldm4(base + 4*PJ_T + boff + kt*32);
                    uint4 B1 = ldm4(base + 4*PJ_T + boff + 2304 + kt*32);
#pragma unroll
                    for (int mf = 0; mf < 4; mf++) {
                        mmaA(c1[mf*4+0], A[mf], B0.x, B0.y);
                        mmaA(c1[mf*4+1], A[mf], B0.z, B0.w);
                        mmaA(c1[mf*4+2], A[mf], B1.x, B1.y);
                        mmaA(c1[mf*4+3], A[mf], B1.z, B1.w);
                    }
                }
            }
        } else {
#pragma unroll
            for (int kt = 0; kt < 4; kt++) {
                uint4 A[4], AL[4];
#pragma unroll
                for (int mf = 0; mf < 4; mf++) {
                    A[mf]  = ldm4(base + aoff + mf*2304 + kt*32);
                    AL[mf] = ldm4(base + PJ_T + aoff + mf*2304 + kt*32);
                }
                uint4 Bh0 = ldm4(base + 2*PJ_T + boff + kt*32);
                uint4 Bh1 = ldm4(base + 2*PJ_T + boff + 2304 + kt*32);
                uint4 Bl0 = ldm4(base + 3*PJ_T + boff + kt*32);
                uint4 Bl1 = ldm4(base + 3*PJ_T + boff + 2304 + kt*32);
#pragma unroll
                for (int mf = 0; mf < 4; mf++) {
                    mmaA(c0[mf*4+0], A[mf], Bh0.x, Bh0.y);
                    mmaA(c0[mf*4+1], A[mf], Bh0.z, Bh0.w);
                    mmaA(c0[mf*4+2], A[mf], Bh1.x, Bh1.y);
                    mmaA(c0[mf*4+3], A[mf], Bh1.z, Bh1.w);
                }
#pragma unroll
                for (int mf = 0; mf < 4; mf++) {
                    mmaA(c0[mf*4+0], A[mf], Bl0.x, Bl0.y);
                    mmaA(c0[mf*4+1], A[mf], Bl0.z, Bl0.w);
                    mmaA(c0[mf*4+2], A[mf], Bl1.x, Bl1.y);
                    mmaA(c0[mf*4+3], A[mf], Bl1.z, Bl1.w);
                }
#pragma unroll
                for (int mf = 0; mf < 4; mf++) {
                    mmaA(c0[mf*4+0], AL[mf], Bh0.x, Bh0.y);
                    mmaA(c0[mf*4+1], AL[mf], Bh0.z, Bh0.w);
                    mmaA(c0[mf*4+2], AL[mf], Bh1.x, Bh1.y);
                    mmaA(c0[mf*4+3], AL[mf], Bh1.z, Bh1.w);
                }
            }
        }
        __syncthreads();
    }

    if (isqk) {
#pragma unroll
        for (int mf = 0; mf < 4; mf++) {
            size_t rA = (size_t)(row0 + wy*64 + mf*16 + g) * HH;
            size_t rB = rA + 8 * HH;
#pragma unroll
            for (int f = 0; f < 4; f++) {
                int col = wx*32 + (f >> 1)*16 + (f & 1)*8 + tg*2;
                const float* cq = c0[mf*4 + f];
                const float* ck = c1[mf*4 + f];
                u32 qh0 = packbf(cq[0], cq[1]);
                u32 qh1 = packbf(cq[2], cq[3]);
                *(u32*)&g_qh[rA + col] = qh0;
                *(u32*)&g_qh[rB + col] = qh1;
                *(u32*)&g_ql[rA + col] = packlo(cq[0], cq[1], qh0);
                *(u32*)&g_ql[rB + col] = packlo(cq[2], cq[3], qh1);
                *(u32*)&g_kh[rA + col] = packbf(ck[0], ck[1]);
                *(u32*)&g_kh[rB + col] = packbf(ck[2], ck[3]);
            }
        }
    } else {
        float* Cs = (float*)sm;   // [128][132] f32 staging for transpose
#pragma unroll
        for (int mf = 0; mf < 4; mf++) {
            int r = wy*64 + mf*16 + g;
#pragma unroll
            for (int f = 0; f < 4; f++) {
                int col = wx*32 + (f >> 1)*16 + (f & 1)*8 + tg*2;
                const float* cv = c0[mf*4 + f];
                Cs[r * 132 + col]           = cv[0];
                Cs[r * 132 + col + 1]       = cv[1];
                Cs[(r + 8) * 132 + col]     = cv[2];
                Cs[(r + 8) * 132 + col + 1] = cv[3];
            }
        }
        __syncthreads();
        int h = tid >> 1, half = tid & 1;
        int b = row0 >> 11, s0 = row0 & 2047;
        union { __nv_bfloat16 v[64]; uint4 u[8]; } Hh, Ll;
#pragma unroll
        for (int j = 0; j < 64; j++) {
            float f = Cs[(half*64 + j) * 132 + h];
            __nv_bfloat16 hi = __float2bfloat16_rn(f);
            Hh.v[j] = hi;
            Ll.v[j] = __float2bfloat16_rn(f - __bfloat162float(hi));
        }
        size_t ob = ((size_t)(b*HH + h)) * SS + s0 + half*64;
#pragma unroll
        for (int j = 0; j < 8; j++) {
            *(uint4*)&g_vth[ob + j*8] = Hh.u[j];
            *(uint4*)&g_vtl[ob + j*8] = Ll.u[j];
        }
    }
}

// ---------------------------------------------------------------------------
// attn: CTA = 128 Q rows x one batch. 8 warps, warp = 16 rows.
// QK 2-pass with K frags reg-cached; PV 3-pass with Vh frags reg-cached.
// Dropout bits built in-loop from raw drop_u f32 (LDGs hidden under QK MMAs;
// no prepack kernel). smem: Qh,Ql,Kh,Vth,Vtl [128][136] (272B pitch).
// ---------------------------------------------------------------------------
#define AT_T 34816            // 128*136*2
#define ATT_SMEM (5 * AT_T)

__device__ __forceinline__ void tile_load(u32 dst, const __nv_bfloat16* src,
                                          int stride_elems) {
    int tid = threadIdx.x;
#pragma unroll
    for (int i = 0; i < 8; i++) {
        int id = tid + i * 256;
        int r = id >> 4, q = id & 15;
        cpa16(dst + r * 272 + q * 16,
              (const char*)src + (size_t)r * stride_elems * 2 + q * 16);
    }
}

__global__ __launch_bounds__(256) void attn_kernel(
    const float* __restrict__ du_g, float* __restrict__ out)
{
    extern __shared__ char sm[];
    const u32 sb = smem_u32(sm);
    const int tid = threadIdx.x, w = tid >> 5, lane = tid & 31;
    const int g = lane >> 2, tg = lane & 3;
    const int b = blockIdx.y;
    const int q0 = blockIdx.x * 128;

    const u32 Qh = sb, Ql = sb + AT_T, Kh = sb + 2*AT_T;
    const u32 Vh = sb + 3*AT_T, Vl = sb + 4*AT_T;

    const u32 aoff = (u32)((w*16 + (lane & 15)) * 272 + ((lane >> 4) & 1) * 16);
    const u32 boff = (u32)(((lane & 7) + ((lane >> 4) & 1) * 8) * 272 + ((lane >> 3) & 1) * 16);

    const size_t qoff = (size_t)(b*SS + q0) * HH;
    tile_load(Qh, g_qh + qoff, HH);
    tile_load(Ql, g_ql + qoff, HH);
    tile_load(Kh, g_kh + (size_t)(b*SS) * HH, HH);
    CP_COMMIT();

    float o[16][4];
#pragma unroll
    for (int n = 0; n < 16; n++)
#pragma unroll
        for (int j = 0; j < 4; j++) o[n][j] = 0.0f;
    float lsumA = 0.0f, lsumB = 0.0f;

    const float SC = 0.03125f;        // 1024^-0.5
    const float INVK = 1.0f / 0.9f;
    const float* duA = du_g + ((size_t)(b*SS) + q0 + w*16 + g) * SS;
    const float* duB = duA + 8 * SS;

    CP_WAIT(0);
    __syncthreads();

    for (int t = 0; t < 16; t++) {
        const int k0 = t * 128;
        // V(t) load overlaps QK(t)
        tile_load(Vh, g_vth + (size_t)(b*HH) * SS + k0, SS);
        tile_load(Vl, g_vtl + (size_t)(b*HH) * SS + k0, SS);
        CP_COMMIT();

        float c[16][4];
#pragma unroll
        for (int n = 0; n < 16; n++)
#pragma unroll
            for (int j = 0; j < 4; j++) c[n][j] = 0.0f;

        // dropout keep-bits, built per-kt; LDG latency hidden by QK MMAs.
        // bit (2n) = col n*8+tg*2, bit (2n+1) = col n*8+tg*2+1
        u32 wa = 0, wb = 0;

#pragma unroll
        for (int kt = 0; kt < 8; kt++) {
            {
                float2 a0 = *(const float2*)(duA + k0 + kt*16 + tg*2);
                float2 a1 = *(const float2*)(duA + k0 + kt*16 + 8 + tg*2);
                float2 b0 = *(const float2*)(duB + k0 + kt*16 + tg*2);
                float2 b1 = *(const float2*)(duB + k0 + kt*16 + 8 + tg*2);
                wa |= ((a0.x >= 0.1f) ? 1u : 0u) << (4*kt)
                    | ((a0.y >= 0.1f) ? 1u : 0u) << (4*kt+1)
                    | ((a1.x >= 0.1f) ? 1u : 0u) << (4*kt+2)
                    | ((a1.y >= 0.1f) ? 1u : 0u) << (4*kt+3);
                wb |= ((b0.x >= 0.1f) ? 1u : 0u) << (4*kt)
                    | ((b0.y >= 0.1f) ? 1u : 0u) << (4*kt+1)
                    | ((b1.x >= 0.1f) ? 1u : 0u) << (4*kt+2)
                    | ((b1.y >= 0.1f) ? 1u : 0u) << (4*kt+3);
            }
            uint4 AH = ldm4(Qh + aoff + kt*32);
            uint4 AL = ldm4(Ql + aoff + kt*32);
            uint4 kb[8];
#pragma unroll
            for (int np = 0; np < 8; np++) kb[np] = ldm4(Kh + boff + np*4352 + kt*32);
            // pass 1: Qh * Kh
#pragma unroll
            for (int np = 0; np < 8; np++) {
                mmaA(c[2*np], AH, kb[np].x, kb[np].y);
                mmaA(c[2*np+1], AH, kb[np].z, kb[np].w);
            }
            // pass 2: Ql * Kh (reg-cached frags)
#pragma unroll
            for (int np = 0; np < 8; np++) {
                mmaA(c[2*np], AL, kb[np].x, kb[np].y);
                mmaA(c[2*np+1], AL, kb[np].z, kb[np].w);
            }
        }

        CP_WAIT(0);          // V(t) ready
        __syncthreads();     // all warps done reading K(t)
        if (t < 15) {
            tile_load(Kh, g_kh + (size_t)(b*SS + k0 + 128) * HH, HH);
            CP_COMMIT();
        }

        // softmax + dropout(numerator only) + PV
#pragma unroll
        for (int kt = 0; kt < 8; kt++) {
            u32 ph[4], pl[4];
#pragma unroll
            for (int half = 0; half < 2; half++) {
                int n = 2*kt + half;
                int sh = 2*n;
                float p0 = __expf(c[n][0] * SC), p1 = __expf(c[n][1] * SC);
                float p2 = __expf(c[n][2] * SC), p3 = __expf(c[n][3] * SC);
                lsumA += p0 + p1;
                lsumB += p2 + p3;
                p0 *= ((wa >> sh) & 1)     ? INVK : 0.0f;
                p1 *= ((wa >> (sh+1)) & 1) ? INVK : 0.0f;
                p2 *= ((wb >> sh) & 1)     ? INVK : 0.0f;
                p3 *= ((wb >> (sh+1)) & 1) ? INVK : 0.0f;
                ph[2*half]     = packbf(p0, p1);
                pl[2*half]     = packlo(p0, p1, ph[2*half]);
                ph[2*half + 1] = packbf(p2, p3);
                pl[2*half + 1] = packlo(p2, p3, ph[2*half + 1]);
            }
            uint4 vb[8];
#pragma unroll
            for (int np = 0; np < 8; np++) vb[np] = ldm4(Vh + boff + np*4352 + kt*32);
            // pass 1: Ph * Vh
#pragma unroll
            for (int np = 0; np < 8; np++) {
                mma16816(o[2*np], ph[0], ph[1], ph[2], ph[3], vb[np].x, vb[np].y);
                mma16816(o[2*np+1], ph[0], ph[1], ph[2], ph[3], vb[np].z, vb[np].w);
            }
            // pass 2: Ph * Vl (inline loads)
#pragma unroll
            for (int np = 0; np < 8; np++) {
                uint4 B = ldm4(Vl + boff + np*4352 + kt*32);
                mma16816(o[2*np], ph[0], ph[1], ph[2], ph[3], B.x, B.y);
                mma16816(o[2*np+1], ph[0], ph[1], ph[2], ph[3], B.z, B.w);
            }
            // pass 3: Pl * Vh (reg-cached frags)
#pragma unroll
            for (int np = 0; np < 8; np++) {
                mma16816(o[2*np], pl[0], pl[1], pl[2], pl[3], vb[np].x, vb[np].y);
                mma16816(o[2*np+1], pl[0], pl[1], pl[2], pl[3], vb[np].z, vb[np].w);
            }
        }
        if (t < 15) CP_WAIT(0);   // K(t+1) ready
        __syncthreads();          // V buffer reuse safety
    }

    // per-row softmax denominators: reduce over quad lanes
#pragma unroll
    for (int off = 1; off <= 2; off <<= 1) {
        lsumA += __shfl_xor_sync(0xffffffffu, lsumA, off);
        lsumB += __shfl_xor_sync(0xffffffffu, lsumB, off);
    }
    const float invA = 1.0f / lsumA, invB = 1.0f / lsumB;

    float* oA = out + ((size_t)(b*SS) + q0 + w*16 + g) * HH;
    float* oB = oA + 8 * HH;
#pragma unroll
    for (int n = 0; n < 16; n++) {
        int col = n*8 + tg*2;
        *(float2*)(oA + col) = make_float2(o[n][0] * invA, o[n][1] * invA);
        *(float2*)(oB + col) = make_float2(o[n][2] * invB, o[n][3] * invB);
    }
}

extern "C" void kernel_launch(void* const* d_in, const int* in_sizes, int n_in,
                              void* d_out, int out_size)
{
    const float* x  = (const float*)d_in[0];
    const float* wq = (const float*)d_in[1];
    const float* wk = (const float*)d_in[2];
    const float* wv = (const float*)d_in[3];
    const float* du = (const float*)d_in[4];
    float* out = (float*)d_out;

    cudaFuncSetAttribute(proj_kernel, cudaFuncAttributeMaxDynamicSharedMemorySize, PROJ_SMEM);
    cudaFuncSetAttribute(attn_kernel, cudaFuncAttributeMaxDynamicSharedMemorySize, ATT_SMEM);

    wprep_kernel<<<48, 256>>>(wq, wk, wv);
    dim3 g1(BB*SS / 128, 2);
    proj_kernel<<<g1, 256, PROJ_SMEM>>>(x);
    dim3 g2(SS / 128, BB);
    attn_kernel<<<g2, 256, ATT_SMEM>>>(du, out);
}